// round 16
// baseline (speedup 1.0000x reference)
#include <cuda_runtime.h>
#include <math.h>

#define BB 8
#define SS 200
#define HH 4
#define DD 64
#define HID 256
#define NBS (BB*SS)   // 1600

// scratch (device globals; no allocation allowed)
__device__ float g_q[NBS*HID];
__device__ float g_kpos[NBS*HID];
__device__ float g_vpos[NBS*HID];
__device__ float g_qo[BB*HH*SS];
__device__ float g_ko[BB*HH*SS];
__device__ float g_qd[BB*HH*SS];
__device__ float g_kd[BB*HH*SS];
__device__ float g_ctx[NBS*HID];

// ---------------------------------------------------------------------------
// Kernel 1: QKV projection, 8 rows x one matrix per block (grid 200x3),
// split-K x4, float4 weight loads. Reg-capped for 5 blocks/SM.
// ---------------------------------------------------------------------------
__global__ __launch_bounds__(256, 5) void gemm3_kernel(
    const float* __restrict__ x,
    const float* __restrict__ Wq, const float* __restrict__ bq,
    const float* __restrict__ Wk, const float* __restrict__ bk,
    const float* __restrict__ Wv, const float* __restrict__ bv,
    const float* __restrict__ posK, const float* __restrict__ posV,
    const float* __restrict__ order_w, const float* __restrict__ dist_w)
{
    const int r0  = blockIdx.x * 8;
    const int mat = blockIdx.y;
    const float* __restrict__ W    = (mat == 0) ? Wq : (mat == 1) ? Wk : Wv;
    const float* __restrict__ bias = (mat == 0) ? bq : (mat == 1) ? bk : bv;

    const int tid = threadIdx.x;
    const int s   = tid >> 6;
    const int c   = tid & 63;

    __shared__ float xs[HID][8];        // 8KB
    __shared__ float red[3][8][HID];    // 24KB
    __shared__ float fin[8][HID];       // 8KB raw q or k for dot epilogue

    for (int t = tid; t < 8 * HID; t += 256) {
        const int m = t >> 8, g = t & 255;
        xs[g][m] = x[(r0 + m) * HID + g];
    }
    __syncthreads();

    float4 acc[8];
    if (s == 0) {
        const float4 b4 = *(const float4*)&bias[4 * c];
        #pragma unroll
        for (int m = 0; m < 8; m++) acc[m] = b4;
    } else {
        #pragma unroll
        for (int m = 0; m < 8; m++) acc[m] = make_float4(0.f, 0.f, 0.f, 0.f);
    }

    const float* __restrict__ Wp = W + (size_t)(s * 64) * HID + 4 * c;
    const float* __restrict__ xp = &xs[s * 64][0];
    #pragma unroll 4
    for (int gi = 0; gi < 64; gi++) {
        const float4 w = *(const float4*)(Wp + (size_t)gi * HID);
        #pragma unroll
        for (int m = 0; m < 8; m++) {
            const float xv = xp[gi * 8 + m];
            acc[m].x += xv * w.x; acc[m].y += xv * w.y;
            acc[m].z += xv * w.z; acc[m].w += xv * w.w;
        }
    }

    if (s > 0) {
        #pragma unroll
        for (int m = 0; m < 8; m++)
            *(float4*)&red[s - 1][m][4 * c] = acc[m];
    }
    __syncthreads();

    if (s == 0) {
        #pragma unroll
        for (int m = 0; m < 8; m++) {
            const float4 p0 = *(const float4*)&red[0][m][4 * c];
            const float4 p1 = *(const float4*)&red[1][m][4 * c];
            const float4 p2 = *(const float4*)&red[2][m][4 * c];
            float4 a = acc[m];
            a.x += p0.x + p1.x + p2.x;
            a.y += p0.y + p1.y + p2.y;
            a.z += p0.z + p1.z + p2.z;
            a.w += p0.w + p1.w + p2.w;
            const int row = r0 + m;
            const size_t gidx = (size_t)row * HID + 4 * c;
            if (mat == 0) {
                *(float4*)&g_q[gidx] = a;
                *(float4*)&fin[m][4 * c] = a;
            } else if (mat == 1) {
                *(float4*)&fin[m][4 * c] = a;     // raw k for dots
                const float4 pk = *(const float4*)&posK[gidx];
                a.x += pk.x; a.y += pk.y; a.z += pk.z; a.w += pk.w;
                *(float4*)&g_kpos[gidx] = a;
            } else {
                const float4 pv = *(const float4*)&posV[gidx];
                a.x += pv.x; a.y += pv.y; a.z += pv.z; a.w += pv.w;
                *(float4*)&g_vpos[gidx] = a;
            }
        }
    }
    __syncthreads();

    // epilogue: order/dist dots. q-block -> qo/qd; k-block -> ko/kd.
    if (mat < 2) {
        const int w = tid >> 5, l = tid & 31;   // warp w handles row w
        const int obase = (mat == 1) ? 64 : 0;
        const float ow1 = order_w[obase + l], ow2 = order_w[obase + 32 + l];
        const float dw1 = dist_w[obase + l],  dw2 = dist_w[obase + 32 + l];
        const int row = r0 + w;
        const int b = row / SS, sidx = row % SS;
        #pragma unroll
        for (int h = 0; h < HH; h++) {
            const float v1 = fin[w][h * 64 + l];
            const float v2 = fin[w][h * 64 + 32 + l];
            float ao = v1 * ow1 + v2 * ow2;
            float ad = v1 * dw1 + v2 * dw2;
            #pragma unroll
            for (int off = 16; off; off >>= 1) {
                ao += __shfl_xor_sync(0xffffffffu, ao, off);
                ad += __shfl_xor_sync(0xffffffffu, ad, off);
            }
            if (l == 0) {
                const int idx = (b * HH + h) * SS + sidx;
                if (mat == 0) { g_qo[idx] = ao; g_qd[idx] = ad; }
                else          { g_ko[idx] = ao; g_kd[idx] = ad; }
            }
        }
    }
}

// ---------------------------------------------------------------------------
// Kernel 2: FUSED scores + softmax + ctx. ONE i-row per block (grid 1600),
// 256 threads. Probs never leave shared memory. (round-14 proven version)
// ---------------------------------------------------------------------------
__global__ __launch_bounds__(256) void attn_kernel(
    const float* __restrict__ timeK, const float* __restrict__ timeV,
    const float* __restrict__ mask,
    const float* __restrict__ p_order_b, const float* __restrict__ p_dist_b,
    const float* __restrict__ p_scalar)
{
    const int tid = threadIdx.x;
    const int blk = blockIdx.x;
    const int b = blk / SS, i = blk % SS;
    const int w = tid >> 5, l = tid & 31;

    __shared__ float sc[HH][SS];       // scores -> exp (un-normalized)
    __shared__ float q_sh[HID];
    __shared__ float qos[HH], qds[HH];
    __shared__ float inv_s[HH];
    __shared__ float dl[SS];           // log(|d|+1) table
    __shared__ float4 part[3][64];     // ctx partials

    q_sh[tid] = g_q[((size_t)(b * SS + i)) * HID + tid];
    if (tid < HH) {
        qos[tid] = g_qo[(b * HH + tid) * SS + i];
        qds[tid] = g_qd[(b * HH + tid) * SS + i];
    }
    if (tid < SS) dl[tid] = __logf((float)tid + 1.f);
    __syncthreads();

    const float4 q0 = *(const float4*)&q_sh[l * 8];
    const float4 q1 = *(const float4*)&q_sh[l * 8 + 4];
    const int hh = l >> 3;

    const float* tkb = timeK + ((size_t)(b * SS + i)) * SS * HID;
    const float* kpb = g_kpos + (size_t)b * SS * HID;

    // ---- phase 1: raw scores  q . (timeK_ij + kpos_j) ----
    for (int j = w; j < SS; j += 8) {
        const float4* kp = (const float4*)(kpb + (size_t)j * HID);
        const float4* tk = (const float4*)(tkb + (size_t)j * HID);
        const float4 k0 = kp[2 * l], k1 = kp[2 * l + 1];
        const float4 t0 = tk[2 * l], t1 = tk[2 * l + 1];
        float p = q0.x * (t0.x + k0.x) + q0.y * (t0.y + k0.y)
                + q0.z * (t0.z + k0.z) + q0.w * (t0.w + k0.w)
                + q1.x * (t1.x + k1.x) + q1.y * (t1.y + k1.y)
                + q1.z * (t1.z + k1.z) + q1.w * (t1.w + k1.w);
        p += __shfl_xor_sync(0xffffffffu, p, 1);
        p += __shfl_xor_sync(0xffffffffu, p, 2);
        p += __shfl_xor_sync(0xffffffffu, p, 4);
        if ((l & 7) == 0) sc[hh][j] = p;
    }
    __syncthreads();

    // ---- phase 2: order/dist error terms, scale, mask ----
    const float order_b = *p_order_b;
    const float dist_b  = *p_dist_b;
    const float sc2 = p_scalar[0] * p_scalar[0] * 0.5f;
    for (int idx = tid; idx < HH * SS; idx += 256) {
        const int h = idx / SS, j = idx - (idx / SS) * SS;
        const float z = qos[h] + g_ko[(b * HH + h) * SS + j] + order_b;
        const float zz = (j > i) ? -z : z;     // log-sigmoid via softplus
        const float eo = -(fmaxf(zz, 0.f) + __logf(1.f + __expf(-fabsf(zz))));
        const float gd = dl[abs(j - i)];
        const float pd = qds[h] + g_kd[(b * HH + h) * SS + j] + dist_b;
        const float ed = -(gd - pd) * (gd - pd) * sc2;
        sc[h][j] = (sc[h][j] + eo + ed) * 0.125f
                 + mask[((size_t)b * SS + i) * SS + j];
    }
    __syncthreads();

    // ---- phase 3: softmax exp + sums ----
    if (w < HH) {
        float m = -1e30f;
        for (int j = l; j < SS; j += 32) m = fmaxf(m, sc[w][j]);
        #pragma unroll
        for (int off = 16; off; off >>= 1)
            m = fmaxf(m, __shfl_xor_sync(0xffffffffu, m, off));
        float sum = 0.f;
        for (int j = l; j < SS; j += 32) {
            const float e = __expf(sc[w][j] - m);
            sc[w][j] = e;
            sum += e;
        }
        #pragma unroll
        for (int off = 16; off; off >>= 1)
            sum += __shfl_xor_sync(0xffffffffu, sum, off);
        if (l == 0) inv_s[w] = 1.f / sum;
    }
    __syncthreads();

    // ---- phase 4: ctx accumulation (split-j x4); inv_s folded at end ----
    {
        const int grp = tid >> 6;
        const int fq  = tid & 63;
        const int h   = fq >> 4;

        const float4* tv = (const float4*)(timeV + ((size_t)(b * SS + i)) * SS * HID) + fq;
        const float4* vp = (const float4*)(g_vpos + (size_t)b * SS * HID) + fq;
        const float* prow = &sc[h][0];

        const int j0 = grp * (SS / 4);
        float4 acc = make_float4(0.f, 0.f, 0.f, 0.f);
        #pragma unroll 5
        for (int j = j0; j < j0 + SS / 4; j++) {
            const float p = prow[j];
            const float4 t4 = tv[(size_t)j * (HID / 4)];
            const float4 v4 = vp[(size_t)j * (HID / 4)];
            acc.x += p * (t4.x + v4.x);
            acc.y += p * (t4.y + v4.y);
            acc.z += p * (t4.z + v4.z);
            acc.w += p * (t4.w + v4.w);
        }

        if (grp > 0) part[grp - 1][fq] = acc;
        __syncthreads();
        if (grp == 0) {
            #pragma unroll
            for (int g = 0; g < 3; g++) {
                const float4 p4 = part[g][fq];
                acc.x += p4.x; acc.y += p4.y; acc.z += p4.z; acc.w += p4.w;
            }
            const float is = inv_s[h];
            acc.x *= is; acc.y *= is; acc.z *= is; acc.w *= is;
            *(float4*)&g_ctx[((size_t)(b * SS + i)) * HID + 4 * fq] = acc;
        }
    }
}

// ---------------------------------------------------------------------------
// Kernel 3: output projection, 4 rows/block, 512 threads split-K x8,
// grid 400, + residual + LN (fused).
// ---------------------------------------------------------------------------
__global__ __launch_bounds__(512) void outln_kernel(
    const float* __restrict__ x,
    const float* __restrict__ Wd, const float* __restrict__ bd,
    const float* __restrict__ ln_g, const float* __restrict__ ln_b,
    float* __restrict__ out)
{
    const int r0  = blockIdx.x * 4;
    const int tid = threadIdx.x;
    const int s   = tid >> 6;          // k-slice 0..7 (32 k each)
    const int c   = tid & 63;          // col quad

    __shared__ float cs[HID][4];        // 4KB
    __shared__ float red[7][4][HID];    // 28KB
    __shared__ float hsm[4][HID];       // 4KB
    __shared__ float mu[4], rstd[4];

    for (int t = tid; t < 4 * HID; t += 512) {
        const int m = t >> 8, g = t & 255;
        cs[g][m] = g_ctx[(size_t)(r0 + m) * HID + g];
    }
    __syncthreads();

    float4 acc[4];
    if (s == 0) {
        const float4 b4 = *(const float4*)&bd[4 * c];
        #pragma unroll
        for (int m = 0; m < 4; m++) acc[m] = b4;
    } else {
        #pragma unroll
        for (int m = 0; m < 4; m++) acc[m] = make_float4(0.f, 0.f, 0.f, 0.f);
    }

    const float* __restrict__ Wp = Wd + (size_t)(s * 32) * HID + 4 * c;
    const float* __restrict__ xp = &cs[s * 32][0];
    #pragma unroll 4
    for (int gi = 0; gi < 32; gi++) {
        const float4 w = *(const float4*)(Wp + (size_t)gi * HID);
        #pragma unroll
        for (int m = 0; m < 4; m++) {
            const float xv = xp[gi * 4 + m];
            acc[m].x += xv * w.x; acc[m].y += xv * w.y;
            acc[m].z += xv * w.z; acc[m].w += xv * w.w;
        }
    }

    if (s > 0) {
        #pragma unroll
        for (int m = 0; m < 4; m++)
            *(float4*)&red[s - 1][m][4 * c] = acc[m];
    }
    __syncthreads();

    if (s == 0) {
        #pragma unroll
        for (int m = 0; m < 4; m++) {
            float4 a = acc[m];
            #pragma unroll
            for (int p = 0; p < 7; p++) {
                const float4 r = *(const float4*)&red[p][m][4 * c];
                a.x += r.x; a.y += r.y; a.z += r.z; a.w += r.w;
            }
            const float4 xv = *(const float4*)&x[(size_t)(r0 + m) * HID + 4 * c];
            a.x += xv.x; a.y += xv.y; a.z += xv.z; a.w += xv.w;
            *(float4*)&hsm[m][4 * c] = a;
        }
    }
    __syncthreads();

    const int w = tid >> 5, l = tid & 31;
    if (w < 4) {
        float sum = 0.f, sum2 = 0.f;
        #pragma unroll
        for (int t = 0; t < 8; t++) {
            const float v = hsm[w][l + 32 * t];
            sum += v; sum2 += v * v;
        }
        #pragma unroll
        for (int off = 16; off; off >>= 1) {
            sum  += __shfl_xor_sync(0xffffffffu, sum,  off);
            sum2 += __shfl_xor_sync(0xffffffffu, sum2, off);
        }
        if (l == 0) {
            const float m_  = sum / HID;
            const float var = sum2 / HID - m_ * m_;
            mu[w]   = m_;
            rstd[w] = rsqrtf(var + 1e-12f);
        }
    }
    __syncthreads();

    if (tid < 256) {
        const int f = tid;
        const float gf = ln_g[f], bf = ln_b[f];
        #pragma unroll
        for (int m = 0; m < 4; m++)
            out[(size_t)(r0 + m) * HID + f] = (hsm[m][f] - mu[m]) * rstd[m] * gf + bf;
    }
}

// ---------------------------------------------------------------------------
extern "C" void kernel_launch(void* const* d_in, const int* in_sizes, int n_in,
                              void* d_out, int out_size)
{
    const float* x     = (const float*)d_in[0];
    const float* mask  = (const float*)d_in[1];
    const float* posK  = (const float*)d_in[2];
    const float* posV  = (const float*)d_in[3];
    const float* timeK = (const float*)d_in[4];
    const float* timeV = (const float*)d_in[5];
    const float* Wq = (const float*)d_in[6];  const float* bq = (const float*)d_in[7];
    const float* Wk = (const float*)d_in[8];  const float* bk = (const float*)d_in[9];
    const float* Wv = (const float*)d_in[10]; const float* bv = (const float*)d_in[11];
    const float* ow = (const float*)d_in[12]; const float* ob = (const float*)d_in[13];
    const float* dw = (const float*)d_in[14]; const float* db = (const float*)d_in[15];
    const float* sca = (const float*)d_in[16];
    const float* Wd = (const float*)d_in[17]; const float* bd = (const float*)d_in[18];
    const float* lg = (const float*)d_in[19]; const float* lb = (const float*)d_in[20];

    dim3 g1(NBS / 8, 3);
    gemm3_kernel<<<g1, 256>>>(x, Wq, bq, Wk, bk, Wv, bv, posK, posV, ow, dw);
    attn_kernel<<<NBS, 256>>>(timeK, timeV, mask, ob, db, sca);
    outln_kernel<<<NBS / 4, 512>>>(x, Wd, bd, lg, lb, (float*)d_out);
}

// round 17
// speedup vs baseline: 1.2244x; 1.2244x over previous
#include <cuda_runtime.h>
#include <math.h>

#define BB 8
#define SS 200
#define HH 4
#define DD 64
#define HID 256
#define NBS (BB*SS)   // 1600

// scratch (device globals; no allocation allowed)
__device__ float g_q[NBS*HID];
__device__ float g_kpos[NBS*HID];
__device__ float g_vpos[NBS*HID];
__device__ float g_qo[BB*HH*SS];
__device__ float g_ko[BB*HH*SS];
__device__ float g_qd[BB*HH*SS];
__device__ float g_kd[BB*HH*SS];
__device__ float g_ctx[NBS*HID];

// ---------------------------------------------------------------------------
// Kernel 1: QKV projection, 8 rows x one matrix per block (grid 200x3),
// split-K x4, float4 weight loads. Reg-capped to 64 for 4 blocks/SM
// (measured sweet spot; 5-block cap spills).
// ---------------------------------------------------------------------------
__global__ __launch_bounds__(256, 4) void gemm3_kernel(
    const float* __restrict__ x,
    const float* __restrict__ Wq, const float* __restrict__ bq,
    const float* __restrict__ Wk, const float* __restrict__ bk,
    const float* __restrict__ Wv, const float* __restrict__ bv,
    const float* __restrict__ posK, const float* __restrict__ posV,
    const float* __restrict__ order_w, const float* __restrict__ dist_w)
{
    const int r0  = blockIdx.x * 8;
    const int mat = blockIdx.y;
    const float* __restrict__ W    = (mat == 0) ? Wq : (mat == 1) ? Wk : Wv;
    const float* __restrict__ bias = (mat == 0) ? bq : (mat == 1) ? bk : bv;

    const int tid = threadIdx.x;
    const int s   = tid >> 6;
    const int c   = tid & 63;

    __shared__ float xs[HID][8];        // 8KB
    __shared__ float red[3][8][HID];    // 24KB
    __shared__ float fin[8][HID];       // 8KB raw q or k for dot epilogue

    for (int t = tid; t < 8 * HID; t += 256) {
        const int m = t >> 8, g = t & 255;
        xs[g][m] = x[(r0 + m) * HID + g];
    }
    __syncthreads();

    float4 acc[8];
    if (s == 0) {
        const float4 b4 = *(const float4*)&bias[4 * c];
        #pragma unroll
        for (int m = 0; m < 8; m++) acc[m] = b4;
    } else {
        #pragma unroll
        for (int m = 0; m < 8; m++) acc[m] = make_float4(0.f, 0.f, 0.f, 0.f);
    }

    const float* __restrict__ Wp = W + (size_t)(s * 64) * HID + 4 * c;
    const float* __restrict__ xp = &xs[s * 64][0];
    #pragma unroll 4
    for (int gi = 0; gi < 64; gi++) {
        const float4 w = *(const float4*)(Wp + (size_t)gi * HID);
        #pragma unroll
        for (int m = 0; m < 8; m++) {
            const float xv = xp[gi * 8 + m];
            acc[m].x += xv * w.x; acc[m].y += xv * w.y;
            acc[m].z += xv * w.z; acc[m].w += xv * w.w;
        }
    }

    if (s > 0) {
        #pragma unroll
        for (int m = 0; m < 8; m++)
            *(float4*)&red[s - 1][m][4 * c] = acc[m];
    }
    __syncthreads();

    if (s == 0) {
        #pragma unroll
        for (int m = 0; m < 8; m++) {
            const float4 p0 = *(const float4*)&red[0][m][4 * c];
            const float4 p1 = *(const float4*)&red[1][m][4 * c];
            const float4 p2 = *(const float4*)&red[2][m][4 * c];
            float4 a = acc[m];
            a.x += p0.x + p1.x + p2.x;
            a.y += p0.y + p1.y + p2.y;
            a.z += p0.z + p1.z + p2.z;
            a.w += p0.w + p1.w + p2.w;
            const int row = r0 + m;
            const size_t gidx = (size_t)row * HID + 4 * c;
            if (mat == 0) {
                *(float4*)&g_q[gidx] = a;
                *(float4*)&fin[m][4 * c] = a;
            } else if (mat == 1) {
                *(float4*)&fin[m][4 * c] = a;     // raw k for dots
                const float4 pk = *(const float4*)&posK[gidx];
                a.x += pk.x; a.y += pk.y; a.z += pk.z; a.w += pk.w;
                *(float4*)&g_kpos[gidx] = a;
            } else {
                const float4 pv = *(const float4*)&posV[gidx];
                a.x += pv.x; a.y += pv.y; a.z += pv.z; a.w += pv.w;
                *(float4*)&g_vpos[gidx] = a;
            }
        }
    }
    __syncthreads();

    // epilogue: order/dist dots. q-block -> qo/qd; k-block -> ko/kd.
    if (mat < 2) {
        const int w = tid >> 5, l = tid & 31;   // warp w handles row w
        const int obase = (mat == 1) ? 64 : 0;
        const float ow1 = order_w[obase + l], ow2 = order_w[obase + 32 + l];
        const float dw1 = dist_w[obase + l],  dw2 = dist_w[obase + 32 + l];
        const int row = r0 + w;
        const int b = row / SS, sidx = row % SS;
        #pragma unroll
        for (int h = 0; h < HH; h++) {
            const float v1 = fin[w][h * 64 + l];
            const float v2 = fin[w][h * 64 + 32 + l];
            float ao = v1 * ow1 + v2 * ow2;
            float ad = v1 * dw1 + v2 * dw2;
            #pragma unroll
            for (int off = 16; off; off >>= 1) {
                ao += __shfl_xor_sync(0xffffffffu, ao, off);
                ad += __shfl_xor_sync(0xffffffffu, ad, off);
            }
            if (l == 0) {
                const int idx = (b * HH + h) * SS + sidx;
                if (mat == 0) { g_qo[idx] = ao; g_qd[idx] = ad; }
                else          { g_ko[idx] = ao; g_kd[idx] = ad; }
            }
        }
    }
}

// ---------------------------------------------------------------------------
// Kernel 2: FUSED scores + softmax + ctx. ONE i-row per block (grid 1600),
// 256 threads. timeK/timeV read with streaming (evict-first) hints so the
// reused kpos/vpos stay resident in cache.
// ---------------------------------------------------------------------------
__global__ __launch_bounds__(256) void attn_kernel(
    const float* __restrict__ timeK, const float* __restrict__ timeV,
    const float* __restrict__ mask,
    const float* __restrict__ p_order_b, const float* __restrict__ p_dist_b,
    const float* __restrict__ p_scalar)
{
    const int tid = threadIdx.x;
    const int blk = blockIdx.x;
    const int b = blk / SS, i = blk % SS;
    const int w = tid >> 5, l = tid & 31;

    __shared__ float sc[HH][SS];       // scores -> exp (un-normalized)
    __shared__ float q_sh[HID];
    __shared__ float qos[HH], qds[HH];
    __shared__ float inv_s[HH];
    __shared__ float dl[SS];           // log(|d|+1) table
    __shared__ float4 part[3][64];     // ctx partials

    q_sh[tid] = g_q[((size_t)(b * SS + i)) * HID + tid];
    if (tid < HH) {
        qos[tid] = g_qo[(b * HH + tid) * SS + i];
        qds[tid] = g_qd[(b * HH + tid) * SS + i];
    }
    if (tid < SS) dl[tid] = __logf((float)tid + 1.f);
    __syncthreads();

    const float4 q0 = *(const float4*)&q_sh[l * 8];
    const float4 q1 = *(const float4*)&q_sh[l * 8 + 4];
    const int hh = l >> 3;

    const float* tkb = timeK + ((size_t)(b * SS + i)) * SS * HID;
    const float* kpb = g_kpos + (size_t)b * SS * HID;

    // ---- phase 1: raw scores  q . (timeK_ij + kpos_j) ----
    for (int j = w; j < SS; j += 8) {
        const float4* kp = (const float4*)(kpb + (size_t)j * HID);
        const float4* tk = (const float4*)(tkb + (size_t)j * HID);
        const float4 k0 = kp[2 * l], k1 = kp[2 * l + 1];
        const float4 t0 = __ldcs(tk + 2 * l);
        const float4 t1 = __ldcs(tk + 2 * l + 1);
        float p = q0.x * (t0.x + k0.x) + q0.y * (t0.y + k0.y)
                + q0.z * (t0.z + k0.z) + q0.w * (t0.w + k0.w)
                + q1.x * (t1.x + k1.x) + q1.y * (t1.y + k1.y)
                + q1.z * (t1.z + k1.z) + q1.w * (t1.w + k1.w);
        p += __shfl_xor_sync(0xffffffffu, p, 1);
        p += __shfl_xor_sync(0xffffffffu, p, 2);
        p += __shfl_xor_sync(0xffffffffu, p, 4);
        if ((l & 7) == 0) sc[hh][j] = p;
    }
    __syncthreads();

    // ---- phase 2: order/dist error terms, scale, mask ----
    const float order_b = *p_order_b;
    const float dist_b  = *p_dist_b;
    const float sc2 = p_scalar[0] * p_scalar[0] * 0.5f;
    for (int idx = tid; idx < HH * SS; idx += 256) {
        const int h = idx / SS, j = idx - (idx / SS) * SS;
        const float z = qos[h] + g_ko[(b * HH + h) * SS + j] + order_b;
        const float zz = (j > i) ? -z : z;     // log-sigmoid via softplus
        const float eo = -(fmaxf(zz, 0.f) + __logf(1.f + __expf(-fabsf(zz))));
        const float gd = dl[abs(j - i)];
        const float pd = qds[h] + g_kd[(b * HH + h) * SS + j] + dist_b;
        const float ed = -(gd - pd) * (gd - pd) * sc2;
        sc[h][j] = (sc[h][j] + eo + ed) * 0.125f
                 + mask[((size_t)b * SS + i) * SS + j];
    }
    __syncthreads();

    // ---- phase 3: softmax exp + sums ----
    if (w < HH) {
        float m = -1e30f;
        for (int j = l; j < SS; j += 32) m = fmaxf(m, sc[w][j]);
        #pragma unroll
        for (int off = 16; off; off >>= 1)
            m = fmaxf(m, __shfl_xor_sync(0xffffffffu, m, off));
        float sum = 0.f;
        for (int j = l; j < SS; j += 32) {
            const float e = __expf(sc[w][j] - m);
            sc[w][j] = e;
            sum += e;
        }
        #pragma unroll
        for (int off = 16; off; off >>= 1)
            sum += __shfl_xor_sync(0xffffffffu, sum, off);
        if (l == 0) inv_s[w] = 1.f / sum;
    }
    __syncthreads();

    // ---- phase 4: ctx accumulation (split-j x4); inv_s folded at end ----
    {
        const int grp = tid >> 6;
        const int fq  = tid & 63;
        const int h   = fq >> 4;

        const float4* tv = (const float4*)(timeV + ((size_t)(b * SS + i)) * SS * HID) + fq;
        const float4* vp = (const float4*)(g_vpos + (size_t)b * SS * HID) + fq;
        const float* prow = &sc[h][0];

        const int j0 = grp * (SS / 4);
        float4 acc = make_float4(0.f, 0.f, 0.f, 0.f);
        #pragma unroll 5
        for (int j = j0; j < j0 + SS / 4; j++) {
            const float p = prow[j];
            const float4 t4 = __ldcs(tv + (size_t)j * (HID / 4));
            const float4 v4 = vp[(size_t)j * (HID / 4)];
            acc.x += p * (t4.x + v4.x);
            acc.y += p * (t4.y + v4.y);
            acc.z += p * (t4.z + v4.z);
            acc.w += p * (t4.w + v4.w);
        }

        if (grp > 0) part[grp - 1][fq] = acc;
        __syncthreads();
        if (grp == 0) {
            #pragma unroll
            for (int g = 0; g < 3; g++) {
                const float4 p4 = part[g][fq];
                acc.x += p4.x; acc.y += p4.y; acc.z += p4.z; acc.w += p4.w;
            }
            const float is = inv_s[h];
            acc.x *= is; acc.y *= is; acc.z *= is; acc.w *= is;
            *(float4*)&g_ctx[((size_t)(b * SS + i)) * HID + 4 * fq] = acc;
        }
    }
}

// ---------------------------------------------------------------------------
// Kernel 3: output projection, 4 rows/block, 512 threads split-K x8,
// grid 400, + residual + LN (fused).
// ---------------------------------------------------------------------------
__global__ __launch_bounds__(512) void outln_kernel(
    const float* __restrict__ x,
    const float* __restrict__ Wd, const float* __restrict__ bd,
    const float* __restrict__ ln_g, const float* __restrict__ ln_b,
    float* __restrict__ out)
{
    const int r0  = blockIdx.x * 4;
    const int tid = threadIdx.x;
    const int s   = tid >> 6;          // k-slice 0..7 (32 k each)
    const int c   = tid & 63;          // col quad

    __shared__ float cs[HID][4];        // 4KB
    __shared__ float red[7][4][HID];    // 28KB
    __shared__ float hsm[4][HID];       // 4KB
    __shared__ float mu[4], rstd[4];

    for (int t = tid; t < 4 * HID; t += 512) {
        const int m = t >> 8, g = t & 255;
        cs[g][m] = g_ctx[(size_t)(r0 + m) * HID + g];
    }
    __syncthreads();

    float4 acc[4];
    if (s == 0) {
        const float4 b4 = *(const float4*)&bd[4 * c];
        #pragma unroll
        for (int m = 0; m < 4; m++) acc[m] = b4;
    } else {
        #pragma unroll
        for (int m = 0; m < 4; m++) acc[m] = make_float4(0.f, 0.f, 0.f, 0.f);
    }

    const float* __restrict__ Wp = Wd + (size_t)(s * 32) * HID + 4 * c;
    const float* __restrict__ xp = &cs[s * 32][0];
    #pragma unroll 4
    for (int gi = 0; gi < 32; gi++) {
        const float4 w = *(const float4*)(Wp + (size_t)gi * HID);
        #pragma unroll
        for (int m = 0; m < 4; m++) {
            const float xv = xp[gi * 4 + m];
            acc[m].x += xv * w.x; acc[m].y += xv * w.y;
            acc[m].z += xv * w.z; acc[m].w += xv * w.w;
        }
    }

    if (s > 0) {
        #pragma unroll
        for (int m = 0; m < 4; m++)
            *(float4*)&red[s - 1][m][4 * c] = acc[m];
    }
    __syncthreads();

    if (s == 0) {
        #pragma unroll
        for (int m = 0; m < 4; m++) {
            float4 a = acc[m];
            #pragma unroll
            for (int p = 0; p < 7; p++) {
                const float4 r = *(const float4*)&red[p][m][4 * c];
                a.x += r.x; a.y += r.y; a.z += r.z; a.w += r.w;
            }
            const float4 xv = *(const float4*)&x[(size_t)(r0 + m) * HID + 4 * c];
            a.x += xv.x; a.y += xv.y; a.z += xv.z; a.w += xv.w;
            *(float4*)&hsm[m][4 * c] = a;
        }
    }
    __syncthreads();

    const int w = tid >> 5, l = tid & 31;
    if (w < 4) {
        float sum = 0.f, sum2 = 0.f;
        #pragma unroll
        for (int t = 0; t < 8; t++) {
            const float v = hsm[w][l + 32 * t];
            sum += v; sum2 += v * v;
        }
        #pragma unroll
        for (int off = 16; off; off >>= 1) {
            sum  += __shfl_xor_sync(0xffffffffu, sum,  off);
            sum2 += __shfl_xor_sync(0xffffffffu, sum2, off);
        }
        if (l == 0) {
            const float m_  = sum / HID;
            const float var = sum2 / HID - m_ * m_;
            mu[w]   = m_;
            rstd[w] = rsqrtf(var + 1e-12f);
        }
    }
    __syncthreads();

    if (tid < 256) {
        const int f = tid;
        const float gf = ln_g[f], bf = ln_b[f];
        #pragma unroll
        for (int m = 0; m < 4; m++)
            out[(size_t)(r0 + m) * HID + f] = (hsm[m][f] - mu[m]) * rstd[m] * gf + bf;
    }
}

// ---------------------------------------------------------------------------
extern "C" void kernel_launch(void* const* d_in, const int* in_sizes, int n_in,
                              void* d_out, int out_size)
{
    const float* x     = (const float*)d_in[0];
    const float* mask  = (const float*)d_in[1];
    const float* posK  = (const float*)d_in[2];
    const float* posV  = (const float*)d_in[3];
    const float* timeK = (const float*)d_in[4];
    const float* timeV = (const float*)d_in[5];
    const float* Wq = (const float*)d_in[6];  const float* bq = (const float*)d_in[7];
    const float* Wk = (const float*)d_in[8];  const float* bk = (const float*)d_in[9];
    const float* Wv = (const float*)d_in[10]; const float* bv = (const float*)d_in[11];
    const float* ow = (const float*)d_in[12]; const float* ob = (const float*)d_in[13];
    const float* dw = (const float*)d_in[14]; const float* db = (const float*)d_in[15];
    const float* sca = (const float*)d_in[16];
    const float* Wd = (const float*)d_in[17]; const float* bd = (const float*)d_in[18];
    const float* lg = (const float*)d_in[19]; const float* lb = (const float*)d_in[20];

    dim3 g1(NBS / 8, 3);
    gemm3_kernel<<<g1, 256>>>(x, Wq, bq, Wk, bk, Wv, bv, posK, posV, ow, dw);
    attn_kernel<<<NBS, 256>>>(timeK, timeV, mask, ob, db, sca);
    outln_kernel<<<NBS / 4, 512>>>(x, Wd, bd, lg, lb, (float*)d_out);
}